// round 6
// baseline (speedup 1.0000x reference)
#include <cuda_runtime.h>
#include <cuda_bf16.h>
#include <math.h>

// Problem constants
#define BATCH 4
#define SEQ 2048
#define DMODEL 512
#define NHEADS 8
#define DK 64
#define MROWS (BATCH * SEQ)   // 8192

// ---------------- scratch (static device globals; no allocation allowed) ---------
// NOTE: these must ONLY be referenced from device code. Passing them as kernel
// arguments from host code passes the host shadow symbol (and on GB300 with ATS
// the device write silently lands in host memory) — that was the round-2/4 bug.
__device__ float g_Q[BATCH * NHEADS * SEQ * DK];    // head-major [B,H,N,64]
__device__ float g_K[BATCH * NHEADS * SEQ * DK];
__device__ float g_V[BATCH * NHEADS * SEQ * DK];
__device__ float g_attn[MROWS * DMODEL];            // flat [8192,512]

// =================================================================================
// GEMM: out = X[8192,512] * W[512,512] + bias, 128x128x16 tile, 8x8 per thread
// MODE 0: write head-major scratch (for Q/K/V). MODE 1: flat row-major.
// =================================================================================
template <int MODE>
__device__ __forceinline__ void gemm_body(const float* __restrict__ X,
                                          const float* __restrict__ W,
                                          const float* __restrict__ bias,
                                          float* __restrict__ out)
{
    __shared__ float As[16 * 128];   // As[k][m]
    __shared__ float Bs[16 * 128];   // Bs[k][n]

    const int tid = threadIdx.x;
    const int rowBase = blockIdx.y * 128;
    const int colBase = blockIdx.x * 128;

    const int ty = tid >> 4;     // 0..15
    const int tx = tid & 15;     // 0..15

    // A loader: 64 rows per pass, 4 cols (float4) per thread
    const int aRow = tid >> 2;          // 0..63
    const int aCol = (tid & 3) << 2;    // 0,4,8,12
    // B loader: 8 rows per pass, 128 cols via float4
    const int bRow = tid >> 5;          // 0..7
    const int bCol = (tid & 31) << 2;   // 0..124

    float acc[8][8];
#pragma unroll
    for (int i = 0; i < 8; i++)
#pragma unroll
        for (int j = 0; j < 8; j++) acc[i][j] = 0.0f;

    for (int k0 = 0; k0 < DMODEL; k0 += 16) {
        // load A tile (128x16) transposed into As[k][m]
#pragma unroll
        for (int p = 0; p < 2; p++) {
            const int r = rowBase + aRow + p * 64;
            const float4 v = *reinterpret_cast<const float4*>(&X[(size_t)r * DMODEL + k0 + aCol]);
            As[(aCol + 0) * 128 + aRow + p * 64] = v.x;
            As[(aCol + 1) * 128 + aRow + p * 64] = v.y;
            As[(aCol + 2) * 128 + aRow + p * 64] = v.z;
            As[(aCol + 3) * 128 + aRow + p * 64] = v.w;
        }
        // load B tile (16x128) into Bs[k][n]
#pragma unroll
        for (int p = 0; p < 2; p++) {
            const int k = k0 + bRow + p * 8;
            const float4 v = *reinterpret_cast<const float4*>(&W[(size_t)k * DMODEL + colBase + bCol]);
            *reinterpret_cast<float4*>(&Bs[(bRow + p * 8) * 128 + bCol]) = v;
        }
        __syncthreads();

#pragma unroll
        for (int k = 0; k < 16; k++) {
            const float4 a0 = *reinterpret_cast<const float4*>(&As[k * 128 + ty * 4]);
            const float4 a1 = *reinterpret_cast<const float4*>(&As[k * 128 + 64 + ty * 4]);
            const float4 b0 = *reinterpret_cast<const float4*>(&Bs[k * 128 + tx * 4]);
            const float4 b1 = *reinterpret_cast<const float4*>(&Bs[k * 128 + 64 + tx * 4]);
            const float av[8] = {a0.x, a0.y, a0.z, a0.w, a1.x, a1.y, a1.z, a1.w};
            const float bv[8] = {b0.x, b0.y, b0.z, b0.w, b1.x, b1.y, b1.z, b1.w};
#pragma unroll
            for (int i = 0; i < 8; i++)
#pragma unroll
                for (int j = 0; j < 8; j++)
                    acc[i][j] = fmaf(av[i], bv[j], acc[i][j]);
        }
        __syncthreads();
    }

    // epilogue
#pragma unroll
    for (int i = 0; i < 8; i++) {
        const int r = rowBase + ((i < 4) ? (ty * 4 + i) : (64 + ty * 4 + i - 4));
#pragma unroll
        for (int j = 0; j < 8; j++) {
            const int c = colBase + ((j < 4) ? (tx * 4 + j) : (64 + tx * 4 + j - 4));
            const float val = acc[i][j] + bias[c];
            if (MODE == 0) {
                const int b = r >> 11;          // /2048
                const int n = r & 2047;
                const int h = c >> 6;           // /64
                const int d = c & 63;
                out[(((size_t)(b * NHEADS + h) * SEQ) + n) * DK + d] = val;
            } else {
                out[(size_t)r * DMODEL + c] = val;
            }
        }
    }
}

__global__ void __launch_bounds__(256)
gemm_qkv_kernel(const float* __restrict__ X,
                const float* __restrict__ Wq, const float* __restrict__ Wk,
                const float* __restrict__ Wv,
                const float* __restrict__ bq, const float* __restrict__ bk,
                const float* __restrict__ bv)
{
    const int z = blockIdx.z;
    const float* W = (z == 0) ? Wq : (z == 1) ? Wk : Wv;
    const float* bias = (z == 0) ? bq : (z == 1) ? bk : bv;
    float* out = (z == 0) ? g_Q : (z == 1) ? g_K : g_V;   // device-code reference: real device address
    gemm_body<0>(X, W, bias, out);
}

__global__ void __launch_bounds__(256)
gemm_out_kernel(const float* __restrict__ Wo, const float* __restrict__ bo,
                float* __restrict__ out)
{
    gemm_body<1>(g_attn, Wo, bo, out);
}

// =================================================================================
// Flash attention with STATIC shared memory (<= 48KB) and NO pointer parameters —
// g_Q/g_K/g_V/g_attn are referenced directly from device code.
// BQ = 64 query rows per CTA, BKV = 32 keys per iteration (64 iterations).
// 256 threads as 16x16: thread (ty,tx) owns S rows ty*4..+3 x cols tx*2..+1,
// and O rows ty*4..+3 x cols tx*4..+3. Online softmax with width-16 shuffles.
// Static smem: Qs 64x65 + Ks 32x65 + Vs 32x65 + Ps 64x33 = 41,728 bytes.
// =================================================================================
#define BQ 64
#define BKV 32
#define PADQ 65
#define PADK 65
#define PADP 33

__global__ void __launch_bounds__(256)
flash_kernel()
{
    __shared__ float Qs[BQ * PADQ];
    __shared__ float Ks[BKV * PADK];
    __shared__ float Vs[BKV * PADK];
    __shared__ float Ps[BQ * PADP];

    const int tid = threadIdx.x;
    const int ty = tid >> 4;      // 0..15
    const int tx = tid & 15;      // 0..15
    const int r0 = ty * 4;        // S/O rows
    const int cs = tx * 2;        // S cols (2 per thread)
    const int co = tx * 4;        // O cols (4 per thread)

    const int qt = blockIdx.x;    // 0..31
    const int h  = blockIdx.y;    // 0..7
    const int b  = blockIdx.z;    // 0..3
    const int q0 = qt * BQ;

    const size_t headBase = (size_t)(b * NHEADS + h) * SEQ * DK;
    const float scale = 0.125f;   // 1/sqrt(64)

    // load Q tile (64x64 floats = 1024 float4, 4 per thread), scaled
    {
        const float* Qg = g_Q + headBase + (size_t)q0 * DK;
#pragma unroll
        for (int p = 0; p < 4; p++) {
            const int e = p * 256 + tid;
            const int row = e >> 4;
            const int c4 = (e & 15) << 2;
            const float4 v = *reinterpret_cast<const float4*>(&Qg[row * DK + c4]);
            Qs[row * PADQ + c4 + 0] = v.x * scale;
            Qs[row * PADQ + c4 + 1] = v.y * scale;
            Qs[row * PADQ + c4 + 2] = v.z * scale;
            Qs[row * PADQ + c4 + 3] = v.w * scale;
        }
    }

    float m[4], l[4], o[4][4];
#pragma unroll
    for (int i = 0; i < 4; i++) {
        m[i] = -INFINITY; l[i] = 0.0f;
#pragma unroll
        for (int j = 0; j < 4; j++) o[i][j] = 0.0f;
    }

    for (int kt = 0; kt < SEQ / BKV; kt++) {
        const int kv0 = kt * BKV;
        const float* Kg = g_K + headBase + (size_t)kv0 * DK;
        const float* Vg = g_V + headBase + (size_t)kv0 * DK;

        __syncthreads();   // all readers of previous Ks/Vs/Ps done
        // load K and V tiles: 32x64 floats = 512 float4 each, 2 per thread
#pragma unroll
        for (int p = 0; p < 2; p++) {
            const int e = p * 256 + tid;
            const int row = e >> 4;
            const int c4 = (e & 15) << 2;
            const float4 kv = *reinterpret_cast<const float4*>(&Kg[row * DK + c4]);
            Ks[row * PADK + c4 + 0] = kv.x;
            Ks[row * PADK + c4 + 1] = kv.y;
            Ks[row * PADK + c4 + 2] = kv.z;
            Ks[row * PADK + c4 + 3] = kv.w;
            const float4 vv = *reinterpret_cast<const float4*>(&Vg[row * DK + c4]);
            Vs[row * PADK + c4 + 0] = vv.x;
            Vs[row * PADK + c4 + 1] = vv.y;
            Vs[row * PADK + c4 + 2] = vv.z;
            Vs[row * PADK + c4 + 3] = vv.w;
        }
        __syncthreads();

        // S = Q * K^T  (4 rows x 2 cols per thread)
        float s[4][2];
#pragma unroll
        for (int i = 0; i < 4; i++) { s[i][0] = 0.0f; s[i][1] = 0.0f; }

#pragma unroll 8
        for (int d = 0; d < DK; d++) {
            float q[4], k[2];
#pragma unroll
            for (int i = 0; i < 4; i++) q[i] = Qs[(r0 + i) * PADQ + d];
            k[0] = Ks[(cs + 0) * PADK + d];
            k[1] = Ks[(cs + 1) * PADK + d];
#pragma unroll
            for (int i = 0; i < 4; i++) {
                s[i][0] = fmaf(q[i], k[0], s[i][0]);
                s[i][1] = fmaf(q[i], k[1], s[i][1]);
            }
        }

        // online softmax update (row spread across 16 tx lanes)
#pragma unroll
        for (int i = 0; i < 4; i++) {
            float tm = fmaxf(s[i][0], s[i][1]);
#pragma unroll
            for (int off = 8; off >= 1; off >>= 1)
                tm = fmaxf(tm, __shfl_xor_sync(0xffffffffu, tm, off, 16));

            const float m_new = fmaxf(m[i], tm);
            const float corr = __expf(m[i] - m_new);
            const float p0 = __expf(s[i][0] - m_new);
            const float p1 = __expf(s[i][1] - m_new);
            float rsum = p0 + p1;
#pragma unroll
            for (int off = 8; off >= 1; off >>= 1)
                rsum += __shfl_xor_sync(0xffffffffu, rsum, off, 16);

            l[i] = l[i] * corr + rsum;
            m[i] = m_new;
#pragma unroll
            for (int j = 0; j < 4; j++) o[i][j] *= corr;
            Ps[(r0 + i) * PADP + cs + 0] = p0;
            Ps[(r0 + i) * PADP + cs + 1] = p1;
        }
        __syncthreads();

        // O += P * V  (output cols co..co+3)
#pragma unroll 8
        for (int j = 0; j < BKV; j++) {
            float vj[4];
#pragma unroll
            for (int dd = 0; dd < 4; dd++) vj[dd] = Vs[j * PADK + co + dd];
#pragma unroll
            for (int i = 0; i < 4; i++) {
                const float pv = Ps[(r0 + i) * PADP + j];
#pragma unroll
                for (int dd = 0; dd < 4; dd++)
                    o[i][dd] = fmaf(pv, vj[dd], o[i][dd]);
            }
        }
    }

    // write normalized output to flat [8192, 512] (device-code reference to g_attn)
#pragma unroll
    for (int i = 0; i < 4; i++) {
        const float inv = 1.0f / l[i];
        const int row = b * SEQ + q0 + r0 + i;
#pragma unroll
        for (int dd = 0; dd < 4; dd++) {
            const int col = h * DK + co + dd;
            g_attn[(size_t)row * DMODEL + col] = o[i][dd] * inv;
        }
    }
}

// =================================================================================
// launch
// =================================================================================
extern "C" void kernel_launch(void* const* d_in, const int* in_sizes, int n_in,
                              void* d_out, int out_size)
{
    const float* x  = (const float*)d_in[0];
    const float* Wq = (const float*)d_in[1];
    const float* bq = (const float*)d_in[2];
    const float* Wk = (const float*)d_in[3];
    const float* bk = (const float*)d_in[4];
    const float* Wv = (const float*)d_in[5];
    const float* bv = (const float*)d_in[6];
    const float* Wo = (const float*)d_in[7];
    const float* bo = (const float*)d_in[8];
    float* out = (float*)d_out;

    // 1) QKV projections into head-major scratch
    dim3 gQKV(DMODEL / 128, MROWS / 128, 3);
    gemm_qkv_kernel<<<gQKV, 256>>>(x, Wq, Wk, Wv, bq, bk, bv);

    // 2) flash attention -> g_attn (flat [8192, 512])
    dim3 gF(SEQ / BQ, NHEADS, BATCH);
    flash_kernel<<<gF, 256>>>();

    // 3) output projection -> d_out
    dim3 gO(DMODEL / 128, MROWS / 128);
    gemm_out_kernel<<<gO, 256>>>(Wo, bo, out);
}

// round 8
// speedup vs baseline: 2.1762x; 2.1762x over previous
#include <cuda_runtime.h>
#include <cuda_bf16.h>
#include <math.h>

// Problem constants
#define BATCH 4
#define SEQ 2048
#define DMODEL 512
#define NHEADS 8
#define DK 64
#define MROWS (BATCH * SEQ)   // 8192

// ---------------- scratch (static device globals; no allocation allowed) ---------
// NOTE: referenced ONLY from device code (host-side use passes the shadow symbol
// and on GB300/ATS writes silently land in host memory — round-2/4 bug).
__device__ float g_Q[BATCH * NHEADS * SEQ * DK];    // head-major [B,H,N,64]
__device__ float g_K[BATCH * NHEADS * SEQ * DK];
__device__ float g_V[BATCH * NHEADS * SEQ * DK];
__device__ float g_attn[MROWS * DMODEL];            // flat [8192,512]

// =================================================================================
// GEMM: out = X[8192,512] * W[512,512] + bias, 128x128x16 tile, 8x8 per thread
// MODE 0: write head-major scratch (for Q/K/V). MODE 1: flat row-major.
// (known-good from round 6; untouched)
// =================================================================================
template <int MODE>
__device__ __forceinline__ void gemm_body(const float* __restrict__ X,
                                          const float* __restrict__ W,
                                          const float* __restrict__ bias,
                                          float* __restrict__ out)
{
    __shared__ float As[16 * 128];   // As[k][m]
    __shared__ float Bs[16 * 128];   // Bs[k][n]

    const int tid = threadIdx.x;
    const int rowBase = blockIdx.y * 128;
    const int colBase = blockIdx.x * 128;

    const int ty = tid >> 4;     // 0..15
    const int tx = tid & 15;     // 0..15

    const int aRow = tid >> 2;          // 0..63
    const int aCol = (tid & 3) << 2;    // 0,4,8,12
    const int bRow = tid >> 5;          // 0..7
    const int bCol = (tid & 31) << 2;   // 0..124

    float acc[8][8];
#pragma unroll
    for (int i = 0; i < 8; i++)
#pragma unroll
        for (int j = 0; j < 8; j++) acc[i][j] = 0.0f;

    for (int k0 = 0; k0 < DMODEL; k0 += 16) {
#pragma unroll
        for (int p = 0; p < 2; p++) {
            const int r = rowBase + aRow + p * 64;
            const float4 v = *reinterpret_cast<const float4*>(&X[(size_t)r * DMODEL + k0 + aCol]);
            As[(aCol + 0) * 128 + aRow + p * 64] = v.x;
            As[(aCol + 1) * 128 + aRow + p * 64] = v.y;
            As[(aCol + 2) * 128 + aRow + p * 64] = v.z;
            As[(aCol + 3) * 128 + aRow + p * 64] = v.w;
        }
#pragma unroll
        for (int p = 0; p < 2; p++) {
            const int k = k0 + bRow + p * 8;
            const float4 v = *reinterpret_cast<const float4*>(&W[(size_t)k * DMODEL + colBase + bCol]);
            *reinterpret_cast<float4*>(&Bs[(bRow + p * 8) * 128 + bCol]) = v;
        }
        __syncthreads();

#pragma unroll
        for (int k = 0; k < 16; k++) {
            const float4 a0 = *reinterpret_cast<const float4*>(&As[k * 128 + ty * 4]);
            const float4 a1 = *reinterpret_cast<const float4*>(&As[k * 128 + 64 + ty * 4]);
            const float4 b0 = *reinterpret_cast<const float4*>(&Bs[k * 128 + tx * 4]);
            const float4 b1 = *reinterpret_cast<const float4*>(&Bs[k * 128 + 64 + tx * 4]);
            const float av[8] = {a0.x, a0.y, a0.z, a0.w, a1.x, a1.y, a1.z, a1.w};
            const float bv[8] = {b0.x, b0.y, b0.z, b0.w, b1.x, b1.y, b1.z, b1.w};
#pragma unroll
            for (int i = 0; i < 8; i++)
#pragma unroll
                for (int j = 0; j < 8; j++)
                    acc[i][j] = fmaf(av[i], bv[j], acc[i][j]);
        }
        __syncthreads();
    }

#pragma unroll
    for (int i = 0; i < 8; i++) {
        const int r = rowBase + ((i < 4) ? (ty * 4 + i) : (64 + ty * 4 + i - 4));
#pragma unroll
        for (int j = 0; j < 8; j++) {
            const int c = colBase + ((j < 4) ? (tx * 4 + j) : (64 + tx * 4 + j - 4));
            const float val = acc[i][j] + bias[c];
            if (MODE == 0) {
                const int b = r >> 11;
                const int n = r & 2047;
                const int h = c >> 6;
                const int d = c & 63;
                out[(((size_t)(b * NHEADS + h) * SEQ) + n) * DK + d] = val;
            } else {
                out[(size_t)r * DMODEL + c] = val;
            }
        }
    }
}

__global__ void __launch_bounds__(256)
gemm_qkv_kernel(const float* __restrict__ X,
                const float* __restrict__ Wq, const float* __restrict__ Wk,
                const float* __restrict__ Wv,
                const float* __restrict__ bq, const float* __restrict__ bk,
                const float* __restrict__ bv)
{
    const int z = blockIdx.z;
    const float* W = (z == 0) ? Wq : (z == 1) ? Wk : Wv;
    const float* bias = (z == 0) ? bq : (z == 1) ? bk : bv;
    float* out = (z == 0) ? g_Q : (z == 1) ? g_K : g_V;
    gemm_body<0>(X, W, bias, out);
}

__global__ void __launch_bounds__(256)
gemm_out_kernel(const float* __restrict__ Wo, const float* __restrict__ bo,
                float* __restrict__ out)
{
    gemm_body<1>(g_attn, Wo, bo, out);
}

// =================================================================================
// Flash attention on tf32 tensor cores (mma.sync.m16n8k8.row.col.f32.tf32.tf32.f32)
// BQ=64 (4 warps x m16), BKV=32 per iteration.
//  - Q fragments: registers for the whole kernel (8 k-steps x 4 regs).
//  - K in smem [kv][68] (ld=68 => ld%32==4: conflict-free B-frag reads).
//  - V transposed in smem [d][36] (ld=36): B-frags for PV conflict-free.
//  - P staged in warp-private smem [64][36]; only __syncwarp between write/read.
//  - Online softmax on the C-fragment layout, width-4 shuffles (lanes 4r..4r+3).
// smem: 32*68 + 64*36 + 64*36 = 6784 words = 27,136 B (static, no opt-in).
// =================================================================================
#define FBQ 64
#define FBKV 32
#define LDK 68   // 68 % 32 == 4
#define LDV 36   // 36 % 32 == 4
#define LDP 36

__device__ __forceinline__ unsigned f2tf32(float x) {
    unsigned u;
    asm("cvt.rna.tf32.f32 %0, %1;" : "=r"(u) : "f"(x));
    return u;
}

__device__ __forceinline__ void mma_tf32(float* c, const unsigned* a, unsigned b0, unsigned b1) {
    asm volatile(
        "mma.sync.aligned.m16n8k8.row.col.f32.tf32.tf32.f32 "
        "{%0,%1,%2,%3}, {%4,%5,%6,%7}, {%8,%9}, {%0,%1,%2,%3};"
        : "+f"(c[0]), "+f"(c[1]), "+f"(c[2]), "+f"(c[3])
        : "r"(a[0]), "r"(a[1]), "r"(a[2]), "r"(a[3]), "r"(b0), "r"(b1));
}

__global__ void __launch_bounds__(128)
flash_kernel()
{
    __shared__ unsigned Ks[FBKV * LDK];   // K[kv][d], tf32 bits
    __shared__ unsigned Vt[DK * LDV];     // V^T[d][kv], tf32 bits
    __shared__ unsigned Ps[FBQ * LDP];    // P[m][kv], tf32 bits

    const int tid  = threadIdx.x;
    const int lane = tid & 31;
    const int warp = tid >> 5;           // 0..3, rows warp*16..+15
    const int wrow = warp * 16;
    const int lr   = lane >> 2;          // 0..7 fragment row
    const int lc   = lane & 3;           // 0..3 fragment col

    const int q0 = blockIdx.x * FBQ;
    const int h  = blockIdx.y;
    const int b  = blockIdx.z;
    const size_t headBase = (size_t)(b * NHEADS + h) * SEQ * DK;
    const float scale = 0.125f;          // 1/sqrt(64)

    // ---- Q fragments in registers (scaled, tf32) --------------------------------
    unsigned qf[8][4];
    {
        const float* Qg = g_Q + headBase + (size_t)(q0 + wrow) * DK;
#pragma unroll
        for (int ks = 0; ks < 8; ks++) {
            const int c0 = ks * 8 + lc;
            qf[ks][0] = f2tf32(Qg[(lr    ) * DK + c0    ] * scale);
            qf[ks][1] = f2tf32(Qg[(lr + 8) * DK + c0    ] * scale);
            qf[ks][2] = f2tf32(Qg[(lr    ) * DK + c0 + 4] * scale);
            qf[ks][3] = f2tf32(Qg[(lr + 8) * DK + c0 + 4] * scale);
        }
    }

    float m0 = -INFINITY, m1 = -INFINITY, l0 = 0.0f, l1 = 0.0f;
    float o[8][4];
#pragma unroll
    for (int nb = 0; nb < 8; nb++)
#pragma unroll
        for (int c = 0; c < 4; c++) o[nb][c] = 0.0f;

    for (int kt = 0; kt < SEQ / FBKV; kt++) {
        const int kv0 = kt * FBKV;

        __syncthreads();   // all warps done reading Ks/Vt of previous tile

        // K tile -> Ks[kv][d] (tf32). 512 float4 total, 4 per thread.
        {
            const float* Kg = g_K + headBase + (size_t)kv0 * DK;
#pragma unroll
            for (int i = 0; i < 4; i++) {
                const int e  = i * 128 + tid;
                const int kv = e >> 4;
                const int c4 = (e & 15) << 2;
                const float4 v = *reinterpret_cast<const float4*>(&Kg[kv * DK + c4]);
                uint4 u;
                u.x = f2tf32(v.x); u.y = f2tf32(v.y); u.z = f2tf32(v.z); u.w = f2tf32(v.w);
                *reinterpret_cast<uint4*>(&Ks[kv * LDK + c4]) = u;
            }
        }
        // V tile -> Vt[d][kv] transposed (tf32). Per thread: one d, 4 kv-chunks of 4.
        {
            const float* Vg = g_V + headBase + (size_t)kv0 * DK;
            const int d = tid & 63;
            const int g = tid >> 6;   // 0..1
#pragma unroll
            for (int i = 0; i < 4; i++) {
                const int kvb = (i * 2 + g) * 4;
                uint4 u;
                u.x = f2tf32(Vg[(kvb + 0) * DK + d]);
                u.y = f2tf32(Vg[(kvb + 1) * DK + d]);
                u.z = f2tf32(Vg[(kvb + 2) * DK + d]);
                u.w = f2tf32(Vg[(kvb + 3) * DK + d]);
                *reinterpret_cast<uint4*>(&Vt[d * LDV + kvb]) = u;
            }
        }
        __syncthreads();

        // ---- S = Q K^T : 8 k-steps x 4 n-blocks ---------------------------------
        float s[4][4];
#pragma unroll
        for (int nb = 0; nb < 4; nb++)
#pragma unroll
            for (int c = 0; c < 4; c++) s[nb][c] = 0.0f;

#pragma unroll
        for (int ks = 0; ks < 8; ks++) {
#pragma unroll
            for (int nb = 0; nb < 4; nb++) {
                const unsigned b0 = Ks[(nb * 8 + lr) * LDK + ks * 8 + lc];
                const unsigned b1 = Ks[(nb * 8 + lr) * LDK + ks * 8 + lc + 4];
                mma_tf32(s[nb], qf[ks], b0, b1);
            }
        }

        // ---- online softmax (two row-halves: lr and lr+8) -----------------------
#pragma unroll
        for (int hh = 0; hh < 2; hh++) {
            const int ci = hh * 2;   // c indices ci, ci+1 belong to this row half
            float vmax = s[0][ci];
#pragma unroll
            for (int nb = 0; nb < 4; nb++)
                vmax = fmaxf(vmax, fmaxf(s[nb][ci], s[nb][ci + 1]));
            vmax = fmaxf(vmax, __shfl_xor_sync(0xffffffffu, vmax, 1));
            vmax = fmaxf(vmax, __shfl_xor_sync(0xffffffffu, vmax, 2));

            float& m = hh ? m1 : m0;
            float& l = hh ? l1 : l0;
            const float m_new = fmaxf(m, vmax);
            const float corr  = __expf(m - m_new);

            float sum = 0.0f;
            const int prow = wrow + lr + hh * 8;
#pragma unroll
            for (int nb = 0; nb < 4; nb++) {
                const float p0 = __expf(s[nb][ci]     - m_new);
                const float p1 = __expf(s[nb][ci + 1] - m_new);
                sum += p0 + p1;
                const int pcol = nb * 8 + 2 * lc;
                Ps[prow * LDP + pcol]     = f2tf32(p0);
                Ps[prow * LDP + pcol + 1] = f2tf32(p1);
            }
            sum += __shfl_xor_sync(0xffffffffu, sum, 1);
            sum += __shfl_xor_sync(0xffffffffu, sum, 2);

            l = l * corr + sum;
            m = m_new;
#pragma unroll
            for (int nb = 0; nb < 8; nb++) {
                o[nb][ci]     *= corr;
                o[nb][ci + 1] *= corr;
            }
        }
        __syncwarp();   // Ps is warp-private: order STS before LDS within the warp

        // ---- O += P V : 4 k-steps x 8 n-blocks ----------------------------------
#pragma unroll
        for (int ks = 0; ks < 4; ks++) {
            unsigned a[4];
            a[0] = Ps[(wrow + lr    ) * LDP + ks * 8 + lc];
            a[1] = Ps[(wrow + lr + 8) * LDP + ks * 8 + lc];
            a[2] = Ps[(wrow + lr    ) * LDP + ks * 8 + lc + 4];
            a[3] = Ps[(wrow + lr + 8) * LDP + ks * 8 + lc + 4];
#pragma unroll
            for (int nb = 0; nb < 8; nb++) {
                const unsigned b0 = Vt[(nb * 8 + lr) * LDV + ks * 8 + lc];
                const unsigned b1 = Vt[(nb * 8 + lr) * LDV + ks * 8 + lc + 4];
                mma_tf32(o[nb], a, b0, b1);
            }
        }
    }

    // ---- epilogue: normalize and write g_attn [8192, 512] ----------------------
    const float inv0 = 1.0f / l0;
    const float inv1 = 1.0f / l1;
    const int row0 = b * SEQ + q0 + wrow + lr;
    const int row1 = row0 + 8;
#pragma unroll
    for (int nb = 0; nb < 8; nb++) {
        const int col = h * DK + nb * 8 + 2 * lc;
        float2 w0 = make_float2(o[nb][0] * inv0, o[nb][1] * inv0);
        float2 w1 = make_float2(o[nb][2] * inv1, o[nb][3] * inv1);
        *reinterpret_cast<float2*>(&g_attn[(size_t)row0 * DMODEL + col]) = w0;
        *reinterpret_cast<float2*>(&g_attn[(size_t)row1 * DMODEL + col]) = w1;
    }
}

// =================================================================================
// launch
// =================================================================================
extern "C" void kernel_launch(void* const* d_in, const int* in_sizes, int n_in,
                              void* d_out, int out_size)
{
    const float* x  = (const float*)d_in[0];
    const float* Wq = (const float*)d_in[1];
    const float* bq = (const float*)d_in[2];
    const float* Wk = (const float*)d_in[3];
    const float* bk = (const float*)d_in[4];
    const float* Wv = (const float*)d_in[5];
    const float* bv = (const float*)d_in[6];
    const float* Wo = (const float*)d_in[7];
    const float* bo = (const float*)d_in[8];
    float* out = (float*)d_out;

    // 1) QKV projections into head-major scratch
    dim3 gQKV(DMODEL / 128, MROWS / 128, 3);
    gemm_qkv_kernel<<<gQKV, 256>>>(x, Wq, Wk, Wv, bq, bk, bv);

    // 2) flash attention (tf32 tensor cores) -> g_attn
    dim3 gF(SEQ / FBQ, NHEADS, BATCH);
    flash_kernel<<<gF, 128>>>();

    // 3) output projection -> d_out
    dim3 gO(DMODEL / 128, MROWS / 128);
    gemm_out_kernel<<<gO, 256>>>(Wo, bo, out);
}

// round 9
// speedup vs baseline: 3.5095x; 1.6127x over previous
#include <cuda_runtime.h>
#include <cuda_bf16.h>
#include <math.h>

// Problem constants
#define BATCH 4
#define SEQ 2048
#define DMODEL 512
#define NHEADS 8
#define DK 64
#define MROWS (BATCH * SEQ)   // 8192

// ---------------- scratch (static device globals; no allocation allowed) ---------
// NOTE: referenced ONLY from device code (host-side use passes the shadow symbol
// and on GB300/ATS writes silently land in host memory — round-2/4 bug).
__device__ float g_Q[BATCH * NHEADS * SEQ * DK];    // head-major [B,H,N,64]
__device__ float g_K[BATCH * NHEADS * SEQ * DK];
__device__ float g_V[BATCH * NHEADS * SEQ * DK];
__device__ float g_attn[MROWS * DMODEL];            // flat [8192,512]

// ---------------- tf32 mma helpers ----------------------------------------------
__device__ __forceinline__ unsigned f2tf32(float x) {
    unsigned u;
    asm("cvt.rna.tf32.f32 %0, %1;" : "=r"(u) : "f"(x));
    return u;
}

__device__ __forceinline__ void mma_tf32(float* c, const unsigned* a, unsigned b0, unsigned b1) {
    asm volatile(
        "mma.sync.aligned.m16n8k8.row.col.f32.tf32.tf32.f32 "
        "{%0,%1,%2,%3}, {%4,%5,%6,%7}, {%8,%9}, {%0,%1,%2,%3};"
        : "+f"(c[0]), "+f"(c[1]), "+f"(c[2]), "+f"(c[3])
        : "r"(a[0]), "r"(a[1]), "r"(a[2]), "r"(a[3]), "r"(b0), "r"(b1));
}

// =================================================================================
// tf32 GEMM: out = X[8192,512] * W[512,512] + bias
// 128x128 tile, K-step 32, 256 threads = 8 warps in 4(M)x2(N); warp tile 32x64.
// As[m][k] LDA=36 -> A-frag LDS banks 4*lr+lc (conflict-free).
// Bs[k][n] LDB=136 (136%32==8) -> B-frag LDS banks 8*lc+lr (conflict-free),
//   and global W loads stay float4-coalesced (no transpose needed).
// MODE 0: write head-major [B,H,N,64] scratch. MODE 1: flat row-major.
// smem: 128*36*4 + 32*136*4 = 35,840 B (static).
// =================================================================================
#define GLDA 36
#define GLDB 136

template <int MODE>
__device__ __forceinline__ void gemm_tf32_body(const float* __restrict__ X,
                                               const float* __restrict__ W,
                                               const float* __restrict__ bias,
                                               float* __restrict__ out)
{
    __shared__ unsigned As[128 * GLDA];
    __shared__ unsigned Bs[32 * GLDB];

    const int tid  = threadIdx.x;
    const int lane = tid & 31;
    const int warp = tid >> 5;
    const int lr   = lane >> 2;   // 0..7
    const int lc   = lane & 3;    // 0..3
    const int warpM = warp >> 1;  // 0..3 -> m offset *32
    const int warpN = warp & 1;   // 0..1 -> n offset *64

    const int rowBase = blockIdx.y * 128;
    const int colBase = blockIdx.x * 128;

    float acc[2][8][4];
#pragma unroll
    for (int mf = 0; mf < 2; mf++)
#pragma unroll
        for (int nf = 0; nf < 8; nf++)
#pragma unroll
            for (int c = 0; c < 4; c++) acc[mf][nf][c] = 0.0f;

    for (int k0 = 0; k0 < DMODEL; k0 += 32) {
        __syncthreads();   // previous iteration's frag reads done before overwrite
        // A tile: 128x32 -> As[m][k] (tf32). 1024 float4, 4 per thread.
#pragma unroll
        for (int i = 0; i < 4; i++) {
            const int e  = i * 256 + tid;
            const int m  = e >> 3;
            const int k4 = (e & 7) << 2;
            const float4 v = *reinterpret_cast<const float4*>(&X[(size_t)(rowBase + m) * DMODEL + k0 + k4]);
            uint4 u;
            u.x = f2tf32(v.x); u.y = f2tf32(v.y); u.z = f2tf32(v.z); u.w = f2tf32(v.w);
            *reinterpret_cast<uint4*>(&As[m * GLDA + k4]) = u;
        }
        // B tile: 32x128 -> Bs[k][n] (tf32). 1024 float4, 4 per thread.
#pragma unroll
        for (int i = 0; i < 4; i++) {
            const int e  = i * 256 + tid;
            const int k  = e >> 5;
            const int n4 = (e & 31) << 2;
            const float4 v = *reinterpret_cast<const float4*>(&W[(size_t)(k0 + k) * DMODEL + colBase + n4]);
            uint4 u;
            u.x = f2tf32(v.x); u.y = f2tf32(v.y); u.z = f2tf32(v.z); u.w = f2tf32(v.w);
            *reinterpret_cast<uint4*>(&Bs[k * GLDB + n4]) = u;
        }
        __syncthreads();

#pragma unroll
        for (int ks = 0; ks < 4; ks++) {
            unsigned a[2][4];
#pragma unroll
            for (int mf = 0; mf < 2; mf++) {
                const int m0 = warpM * 32 + mf * 16;
                a[mf][0] = As[(m0 + lr    ) * GLDA + ks * 8 + lc];
                a[mf][1] = As[(m0 + lr + 8) * GLDA + ks * 8 + lc];
                a[mf][2] = As[(m0 + lr    ) * GLDA + ks * 8 + lc + 4];
                a[mf][3] = As[(m0 + lr + 8) * GLDA + ks * 8 + lc + 4];
            }
#pragma unroll
            for (int nf = 0; nf < 8; nf++) {
                const int n = warpN * 64 + nf * 8 + lr;
                const unsigned b0 = Bs[(ks * 8 + lc    ) * GLDB + n];
                const unsigned b1 = Bs[(ks * 8 + lc + 4) * GLDB + n];
                mma_tf32(acc[0][nf], a[0], b0, b1);
                mma_tf32(acc[1][nf], a[1], b0, b1);
            }
        }
    }

    // ---- epilogue: bias + store (float2 per frag-row) ---------------------------
#pragma unroll
    for (int mf = 0; mf < 2; mf++) {
        const int r0 = rowBase + warpM * 32 + mf * 16 + lr;
        const int r1 = r0 + 8;
#pragma unroll
        for (int nf = 0; nf < 8; nf++) {
            const int col = colBase + warpN * 64 + nf * 8 + 2 * lc;
            const float2 bb = *reinterpret_cast<const float2*>(&bias[col]);
            float2 v0 = make_float2(acc[mf][nf][0] + bb.x, acc[mf][nf][1] + bb.y);
            float2 v1 = make_float2(acc[mf][nf][2] + bb.x, acc[mf][nf][3] + bb.y);
            if (MODE == 0) {
                const int h = col >> 6;
                const int d = col & 63;
                const int b0r = r0 >> 11, n0r = r0 & 2047;
                const int b1r = r1 >> 11, n1r = r1 & 2047;
                *reinterpret_cast<float2*>(&out[(((size_t)(b0r * NHEADS + h) * SEQ) + n0r) * DK + d]) = v0;
                *reinterpret_cast<float2*>(&out[(((size_t)(b1r * NHEADS + h) * SEQ) + n1r) * DK + d]) = v1;
            } else {
                *reinterpret_cast<float2*>(&out[(size_t)r0 * DMODEL + col]) = v0;
                *reinterpret_cast<float2*>(&out[(size_t)r1 * DMODEL + col]) = v1;
            }
        }
    }
}

__global__ void __launch_bounds__(256)
gemm_qkv_kernel(const float* __restrict__ X,
                const float* __restrict__ Wq, const float* __restrict__ Wk,
                const float* __restrict__ Wv,
                const float* __restrict__ bq, const float* __restrict__ bk,
                const float* __restrict__ bv)
{
    const int z = blockIdx.z;
    const float* W = (z == 0) ? Wq : (z == 1) ? Wk : Wv;
    const float* bias = (z == 0) ? bq : (z == 1) ? bk : bv;
    float* out = (z == 0) ? g_Q : (z == 1) ? g_K : g_V;
    gemm_tf32_body<0>(X, W, bias, out);
}

__global__ void __launch_bounds__(256)
gemm_out_kernel(const float* __restrict__ Wo, const float* __restrict__ bo,
                float* __restrict__ out)
{
    gemm_tf32_body<1>(g_attn, Wo, bo, out);
}

// =================================================================================
// Flash attention on tf32 tensor cores (unchanged from round 8: 706us/2.76e-4)
// BQ=64 (4 warps x m16), BKV=32 per iteration.
// =================================================================================
#define FBQ 64
#define FBKV 32
#define LDK 68   // 68 % 32 == 4
#define LDV 36   // 36 % 32 == 4
#define LDP 36

__global__ void __launch_bounds__(128)
flash_kernel()
{
    __shared__ unsigned Ks[FBKV * LDK];   // K[kv][d], tf32 bits
    __shared__ unsigned Vt[DK * LDV];     // V^T[d][kv], tf32 bits
    __shared__ unsigned Ps[FBQ * LDP];    // P[m][kv], tf32 bits

    const int tid  = threadIdx.x;
    const int lane = tid & 31;
    const int warp = tid >> 5;           // 0..3, rows warp*16..+15
    const int wrow = warp * 16;
    const int lr   = lane >> 2;          // 0..7 fragment row
    const int lc   = lane & 3;           // 0..3 fragment col

    const int q0 = blockIdx.x * FBQ;
    const int h  = blockIdx.y;
    const int b  = blockIdx.z;
    const size_t headBase = (size_t)(b * NHEADS + h) * SEQ * DK;
    const float scale = 0.125f;          // 1/sqrt(64)

    // ---- Q fragments in registers (scaled, tf32) --------------------------------
    unsigned qf[8][4];
    {
        const float* Qg = g_Q + headBase + (size_t)(q0 + wrow) * DK;
#pragma unroll
        for (int ks = 0; ks < 8; ks++) {
            const int c0 = ks * 8 + lc;
            qf[ks][0] = f2tf32(Qg[(lr    ) * DK + c0    ] * scale);
            qf[ks][1] = f2tf32(Qg[(lr + 8) * DK + c0    ] * scale);
            qf[ks][2] = f2tf32(Qg[(lr    ) * DK + c0 + 4] * scale);
            qf[ks][3] = f2tf32(Qg[(lr + 8) * DK + c0 + 4] * scale);
        }
    }

    float m0 = -INFINITY, m1 = -INFINITY, l0 = 0.0f, l1 = 0.0f;
    float o[8][4];
#pragma unroll
    for (int nb = 0; nb < 8; nb++)
#pragma unroll
        for (int c = 0; c < 4; c++) o[nb][c] = 0.0f;

    for (int kt = 0; kt < SEQ / FBKV; kt++) {
        const int kv0 = kt * FBKV;

        __syncthreads();   // all warps done reading Ks/Vt of previous tile

        // K tile -> Ks[kv][d] (tf32). 512 float4 total, 4 per thread.
        {
            const float* Kg = g_K + headBase + (size_t)kv0 * DK;
#pragma unroll
            for (int i = 0; i < 4; i++) {
                const int e  = i * 128 + tid;
                const int kv = e >> 4;
                const int c4 = (e & 15) << 2;
                const float4 v = *reinterpret_cast<const float4*>(&Kg[kv * DK + c4]);
                uint4 u;
                u.x = f2tf32(v.x); u.y = f2tf32(v.y); u.z = f2tf32(v.z); u.w = f2tf32(v.w);
                *reinterpret_cast<uint4*>(&Ks[kv * LDK + c4]) = u;
            }
        }
        // V tile -> Vt[d][kv] transposed (tf32). Per thread: one d, 4 kv-chunks of 4.
        {
            const float* Vg = g_V + headBase + (size_t)kv0 * DK;
            const int d = tid & 63;
            const int g = tid >> 6;   // 0..1
#pragma unroll
            for (int i = 0; i < 4; i++) {
                const int kvb = (i * 2 + g) * 4;
                uint4 u;
                u.x = f2tf32(Vg[(kvb + 0) * DK + d]);
                u.y = f2tf32(Vg[(kvb + 1) * DK + d]);
                u.z = f2tf32(Vg[(kvb + 2) * DK + d]);
                u.w = f2tf32(Vg[(kvb + 3) * DK + d]);
                *reinterpret_cast<uint4*>(&Vt[d * LDV + kvb]) = u;
            }
        }
        __syncthreads();

        // ---- S = Q K^T : 8 k-steps x 4 n-blocks ---------------------------------
        float s[4][4];
#pragma unroll
        for (int nb = 0; nb < 4; nb++)
#pragma unroll
            for (int c = 0; c < 4; c++) s[nb][c] = 0.0f;

#pragma unroll
        for (int ks = 0; ks < 8; ks++) {
#pragma unroll
            for (int nb = 0; nb < 4; nb++) {
                const unsigned b0 = Ks[(nb * 8 + lr) * LDK + ks * 8 + lc];
                const unsigned b1 = Ks[(nb * 8 + lr) * LDK + ks * 8 + lc + 4];
                mma_tf32(s[nb], qf[ks], b0, b1);
            }
        }

        // ---- online softmax (two row-halves: lr and lr+8) -----------------------
#pragma unroll
        for (int hh = 0; hh < 2; hh++) {
            const int ci = hh * 2;   // c indices ci, ci+1 belong to this row half
            float vmax = s[0][ci];
#pragma unroll
            for (int nb = 0; nb < 4; nb++)
                vmax = fmaxf(vmax, fmaxf(s[nb][ci], s[nb][ci + 1]));
            vmax = fmaxf(vmax, __shfl_xor_sync(0xffffffffu, vmax, 1));
            vmax = fmaxf(vmax, __shfl_xor_sync(0xffffffffu, vmax, 2));

            float& m = hh ? m1 : m0;
            float& l = hh ? l1 : l0;
            const float m_new = fmaxf(m, vmax);
            const float corr  = __expf(m - m_new);

            float sum = 0.0f;
            const int prow = wrow + lr + hh * 8;
#pragma unroll
            for (int nb = 0; nb < 4; nb++) {
                const float p0 = __expf(s[nb][ci]     - m_new);
                const float p1 = __expf(s[nb][ci + 1] - m_new);
                sum += p0 + p1;
                const int pcol = nb * 8 + 2 * lc;
                Ps[prow * LDP + pcol]     = f2tf32(p0);
                Ps[prow * LDP + pcol + 1] = f2tf32(p1);
            }
            sum += __shfl_xor_sync(0xffffffffu, sum, 1);
            sum += __shfl_xor_sync(0xffffffffu, sum, 2);

            l = l * corr + sum;
            m = m_new;
#pragma unroll
            for (int nb = 0; nb < 8; nb++) {
                o[nb][ci]     *= corr;
                o[nb][ci + 1] *= corr;
            }
        }
        __syncwarp();   // Ps is warp-private: order STS before LDS within the warp

        // ---- O += P V : 4 k-steps x 8 n-blocks ----------------------------------
#pragma unroll
        for (int ks = 0; ks < 4; ks++) {
            unsigned a[4];
            a[0] = Ps[(wrow + lr    ) * LDP + ks * 8 + lc];
            a[1] = Ps[(wrow + lr + 8) * LDP + ks * 8 + lc];
            a[2] = Ps[(wrow + lr    ) * LDP + ks * 8 + lc + 4];
            a[3] = Ps[(wrow + lr + 8) * LDP + ks * 8 + lc + 4];
#pragma unroll
            for (int nb = 0; nb < 8; nb++) {
                const unsigned b0 = Vt[(nb * 8 + lr) * LDV + ks * 8 + lc];
                const unsigned b1 = Vt[(nb * 8 + lr) * LDV + ks * 8 + lc + 4];
                mma_tf32(o[nb], a, b0, b1);
            }
        }
    }

    // ---- epilogue: normalize and write g_attn [8192, 512] ----------------------
    const float inv0 = 1.0f / l0;
    const float inv1 = 1.0f / l1;
    const int row0 = b * SEQ + q0 + wrow + lr;
    const int row1 = row0 + 8;
#pragma unroll
    for (int nb = 0; nb < 8; nb++) {
        const int col = h * DK + nb * 8 + 2 * lc;
        float2 w0 = make_float2(o[nb][0] * inv0, o[nb][1] * inv0);
        float2 w1 = make_float2(o[nb][2] * inv1, o[nb][3] * inv1);
        *reinterpret_cast<float2*>(&g_attn[(size_t)row0 * DMODEL + col]) = w0;
        *reinterpret_cast<float2*>(&g_attn[(size_t)row1 * DMODEL + col]) = w1;
    }
}

// =================================================================================
// launch
// =================================================================================
extern "C" void kernel_launch(void* const* d_in, const int* in_sizes, int n_in,
                              void* d_out, int out_size)
{
    const float* x  = (const float*)d_in[0];
    const float* Wq = (const float*)d_in[1];
    const float* bq = (const float*)d_in[2];
    const float* Wk = (const float*)d_in[3];
    const float* bk = (const float*)d_in[4];
    const float* Wv = (const float*)d_in[5];
    const float* bv = (const float*)d_in[6];
    const float* Wo = (const float*)d_in[7];
    const float* bo = (const float*)d_in[8];
    float* out = (float*)d_out;

    // 1) QKV projections (tf32 mma) into head-major scratch
    dim3 gQKV(DMODEL / 128, MROWS / 128, 3);
    gemm_qkv_kernel<<<gQKV, 256>>>(x, Wq, Wk, Wv, bq, bk, bv);

    // 2) flash attention (tf32 tensor cores) -> g_attn
    dim3 gF(SEQ / FBQ, NHEADS, BATCH);
    flash_kernel<<<gF, 128>>>();

    // 3) output projection (tf32 mma) -> d_out
    dim3 gO(DMODEL / 128, MROWS / 128);
    gemm_out_kernel<<<gO, 256>>>(Wo, bo, out);
}